// round 15
// baseline (speedup 1.0000x reference)
#include <cuda_runtime.h>
#include <math.h>

// Inverse L2 norms of the two W rows (written by prologue).
__device__ float g_invw[2];

static constexpr float EPS_CLIP = 1e-7f;
static constexpr float SCALE    = 64.0f;
// cos(0.5), sin(0.5)
static constexpr float COS_M = 0.8775825618903728f;
static constexpr float SIN_M = 0.479425538604203f;

// ---------------------------------------------------------------------------
// Prologue: compute ONLY the two inverse norms (8 bytes of output).
// Fires PDL immediately so the main grid launches and runs concurrently.
// One block, 2 warps, one W row per warp.
// ---------------------------------------------------------------------------
__global__ void wnorm_kernel(const float* __restrict__ W) {
    asm volatile("griddepcontrol.launch_dependents;" ::: "memory");

    const int wid  = threadIdx.x >> 5;     // 0 or 1 -> W row
    const int lane = threadIdx.x & 31;

    const float4* __restrict__ w =
        reinterpret_cast<const float4*>(W + wid * 512);

    float ss = 0.0f;
    #pragma unroll
    for (int k = 0; k < 4; k++) {
        float4 v = w[lane + 32 * k];
        ss = fmaf(v.x, v.x, ss); ss = fmaf(v.y, v.y, ss);
        ss = fmaf(v.z, v.z, ss); ss = fmaf(v.w, v.w, ss);
    }
    #pragma unroll
    for (int o = 16; o > 0; o >>= 1) ss += __shfl_xor_sync(0xffffffff, ss, o);

    if (lane == 0) g_invw[wid] = rsqrtf(fmaxf(ss, 1e-24f));
}

// ---------------------------------------------------------------------------
// Main: one warp per feature row (R10 skeleton: 32 regs, 8 warps/block).
// Reads RAW W — no dependency on the prologue until the epilogue, where
// lane 0 needs the two scalar inverse norms. griddepcontrol.wait sits after
// the entire load+FMA+reduce body, so the body fully overlaps the prologue.
// ---------------------------------------------------------------------------
__global__ void __launch_bounds__(256, 8)
arcface_kernel(const float* __restrict__ feat,
               const float* __restrict__ W,
               const int*   __restrict__ label,
               float*       __restrict__ out,
               int B)
{
    const int row  = (blockIdx.x * blockDim.x + threadIdx.x) >> 5;
    const int lane = threadIdx.x & 31;
    if (row >= B) return;

    const float4* __restrict__ f =
        reinterpret_cast<const float4*>(feat + (size_t)row * 512);

    // Front-batch the 4 streaming feat loads.
    float4 a0 = f[lane];
    float4 a1 = f[lane + 32];
    float4 a2 = f[lane + 64];
    float4 a3 = f[lane + 96];

    const float4* __restrict__ w0 = reinterpret_cast<const float4*>(W);
    const float4* __restrict__ w1 = reinterpret_cast<const float4*>(W + 512);

    float ss = 0.0f, d0 = 0.0f, d1 = 0.0f;

    {
        float4 b, c;
        #define ACC(A, K)                                                     \
            b = w0[lane + 32 * (K)];                                          \
            c = w1[lane + 32 * (K)];                                          \
            ss = fmaf(A.x, A.x, ss); ss = fmaf(A.y, A.y, ss);                 \
            ss = fmaf(A.z, A.z, ss); ss = fmaf(A.w, A.w, ss);                 \
            d0 = fmaf(A.x, b.x, d0); d0 = fmaf(A.y, b.y, d0);                 \
            d0 = fmaf(A.z, b.z, d0); d0 = fmaf(A.w, b.w, d0);                 \
            d1 = fmaf(A.x, c.x, d1); d1 = fmaf(A.y, c.y, d1);                 \
            d1 = fmaf(A.z, c.z, d1); d1 = fmaf(A.w, c.w, d1);
        ACC(a0, 0)
        ACC(a1, 1)
        ACC(a2, 2)
        ACC(a3, 3)
        #undef ACC
    }

    #pragma unroll
    for (int o = 16; o > 0; o >>= 1) {
        ss += __shfl_xor_sync(0xffffffff, ss, o);
        d0 += __shfl_xor_sync(0xffffffff, d0, o);
        d1 += __shfl_xor_sync(0xffffffff, d1, o);
    }

    // Only now do we need the prologue's 8 bytes.
    asm volatile("griddepcontrol.wait;" ::: "memory");

    if (lane == 0) {
        const float invf  = rsqrtf(fmaxf(ss, 1e-24f));
        const float invw0 = g_invw[0];
        const float invw1 = g_invw[1];

        float c0 = fminf(fmaxf(d0 * invf * invw0, -1.0f + EPS_CLIP), 1.0f - EPS_CLIP);
        float c1 = fminf(fmaxf(d1 * invf * invw1, -1.0f + EPS_CLIP), 1.0f - EPS_CLIP);

        // cos(theta + m) = cos*cos_m - sin*sin_m, sin = sqrt(1-cos^2) >= 0
        float s0 = sqrtf(fmaxf(1.0f - c0 * c0, 0.0f));
        float s1 = sqrtf(fmaxf(1.0f - c1 * c1, 0.0f));
        float m0 = c0 * COS_M - s0 * SIN_M;
        float m1 = c1 * COS_M - s1 * SIN_M;

        const int lab = label[row];
        float o0 = (lab == 0) ? m0 : c0;
        float o1 = (lab == 1) ? m1 : c1;

        reinterpret_cast<float2*>(out)[row] = make_float2(o0 * SCALE, o1 * SCALE);
    }
}

// ---------------------------------------------------------------------------
// kernel_launch: identify inputs by element count (robust to ordering):
//   feat : B*D f32 (largest), W : C*D f32 (smallest), label : B int32
// PDL launch for the main kernel.
// ---------------------------------------------------------------------------
extern "C" void kernel_launch(void* const* d_in, const int* in_sizes, int n_in,
                              void* d_out, int out_size)
{
    int i_feat = 0, i_w = 0, i_lab = 0;
    for (int i = 1; i < n_in; i++) {
        if (in_sizes[i] > in_sizes[i_feat]) i_feat = i;
        if (in_sizes[i] < in_sizes[i_w])    i_w    = i;
    }
    for (int i = 0; i < n_in; i++)
        if (i != i_feat && i != i_w) i_lab = i;

    const float* feat  = (const float*)d_in[i_feat];
    const float* W     = (const float*)d_in[i_w];
    const int*   label = (const int*)d_in[i_lab];
    float*       out   = (float*)d_out;
    const int    B     = in_sizes[i_lab];

    wnorm_kernel<<<1, 64>>>(W);

    const int blocks = (B + 7) / 8;        // 8 rows (warps) per block

    cudaLaunchConfig_t cfg = {};
    cfg.gridDim  = dim3((unsigned)blocks, 1, 1);
    cfg.blockDim = dim3(256, 1, 1);
    cfg.dynamicSmemBytes = 0;
    cfg.stream = 0;

    cudaLaunchAttribute attr[1];
    attr[0].id = cudaLaunchAttributeProgrammaticStreamSerialization;
    attr[0].val.programmaticStreamSerializationAllowed = 1;
    cfg.attrs = attr;
    cfg.numAttrs = 1;

    cudaLaunchKernelEx(&cfg, arcface_kernel, feat, W, label, out, B);
}